// round 1
// baseline (speedup 1.0000x reference)
#include <cuda_runtime.h>
#include <cstdint>

// L1Attn: out[b,i,j,h] = -(1/sqrt(D)) * sum_d |q[b,j,h,d] - k[b,i,h,d]|
// B=8, S=1024, H=8, D=64. Output layout [B,S,S,H] (i indexes keys, j queries).

namespace {
constexpr int Sdim = 1024;
constexpr int Hh   = 8;
constexpr int Dd   = 64;
constexpr int TJ   = 32;   // j-tile per block (TJ*Hh == blockDim)
constexpr int TI   = 16;   // i-outputs per thread
constexpr int NT   = 256;  // threads per block
constexpr int ROWPAD = 68; // 64 + 4 floats: h-rows land on distinct bank quads

__device__ __forceinline__ unsigned long long addx2(unsigned long long a,
                                                    unsigned long long b) {
    unsigned long long r;
    asm("add.rn.f32x2 %0, %1, %2;" : "=l"(r) : "l"(a), "l"(b));
    return r;
}
}  // namespace

__global__ void __launch_bounds__(NT, 2) l1attn_kernel(
    const float* __restrict__ qg,
    const float* __restrict__ kg,
    float* __restrict__ out)
{
    __shared__ __align__(16) float ks[TI * Hh * ROWPAD];  // 34816 B

    const int t  = threadIdx.x;
    const int j0 = blockIdx.x * TJ;
    const int i0 = blockIdx.y * TI;
    const int b  = blockIdx.z;

    // ---- Stage K tile: rows (i,h) for i in [i0, i0+TI), all h, all d ----
    {
        const size_t kbase = ((size_t)b * Sdim + i0) * (size_t)(Hh * Dd);
        #pragma unroll
        for (int r = 0; r < (TI * Hh * Dd) / (4 * NT); r++) {
            int idx = t + r * NT;        // float4 index 0..2047
            int row = idx >> 4;          // (i*8 + h)
            int dd  = (idx & 15) << 2;
            float4 v = *reinterpret_cast<const float4*>(kg + kbase + row * Dd + dd);
            *reinterpret_cast<float4*>(&ks[row * ROWPAD + dd]) = v;
        }
    }
    __syncthreads();

    const int j = t >> 3;   // 0..31
    const int h = t & 7;    // 0..7

    const unsigned long long SGN = 0x8000000080000000ULL;
    const unsigned long long MSK = 0x7FFFFFFF7FFFFFFFULL;

    const float* qrow = qg + (((size_t)b * Sdim + (j0 + j)) * Hh + h) * Dd;

    unsigned long long acc[TI];
    #pragma unroll
    for (int i = 0; i < TI; i++) acc[i] = 0ULL;

    // d in 4 chunks of 16; keep this loop rolled so the body stays in L0 I$.
    #pragma unroll 1
    for (int c = 0; c < Dd / 16; c++) {
        // Load this thread's q chunk, pre-negated via sign-bit XOR (|q-k| == |k-q|).
        unsigned long long nq[8];
        #pragma unroll
        for (int v = 0; v < 4; v++) {
            ulonglong2 qv = *reinterpret_cast<const ulonglong2*>(qrow + c * 16 + v * 4);
            nq[2 * v]     = qv.x ^ SGN;
            nq[2 * v + 1] = qv.y ^ SGN;
        }
        #pragma unroll
        for (int i = 0; i < TI; i++) {
            const float* kr = &ks[(i * Hh + h) * ROWPAD + c * 16];
            unsigned long long a = acc[i];
            #pragma unroll
            for (int v = 0; v < 4; v++) {
                ulonglong2 kv = *reinterpret_cast<const ulonglong2*>(kr + v * 4);
                unsigned long long t0 = addx2(kv.x, nq[2 * v])     & MSK;  // |k - q| packed
                unsigned long long t1 = addx2(kv.y, nq[2 * v + 1]) & MSK;
                a = addx2(a, t0);
                a = addx2(a, t1);
            }
            acc[i] = a;
        }
    }

    // ---- Epilogue: reduce packed partials, scale, coalesced store ----
    const float scale = -0.125f;  // -1/sqrt(64)
    const size_t obase = (((size_t)b * Sdim + i0) * Sdim + (j0 + j)) * Hh + h;
    #pragma unroll
    for (int i = 0; i < TI; i++) {
        unsigned int lo = (unsigned int)(acc[i] & 0xffffffffu);
        unsigned int hi = (unsigned int)(acc[i] >> 32);
        float r = (__uint_as_float(lo) + __uint_as_float(hi)) * scale;
        out[obase + (size_t)i * (Sdim * Hh)] = r;
    }
}

extern "C" void kernel_launch(void* const* d_in, const int* in_sizes, int n_in,
                              void* d_out, int out_size) {
    const float* q = (const float*)d_in[0];
    const float* k = (const float*)d_in[1];
    float* out     = (float*)d_out;

    const int B = in_sizes[0] / (Sdim * Hh * Dd);  // = 8
    dim3 grid(Sdim / TJ, Sdim / TI, B);
    l1attn_kernel<<<grid, NT>>>(q, k, out);
}

// round 4
// speedup vs baseline: 1.1991x; 1.1991x over previous
#include <cuda_runtime.h>
#include <cstdint>

// L1Attn: out[b,i,j,h] = -(1/8) * sum_d |q[b,j,h,d] - k[b,i,h,d]|
// B=8, S=1024, H=8, D=64. Output [B,S,S,H] (i = keys, j = queries).
//
// Register-tiled: block covers 8 i x 128 j x 8 h; each thread owns one h,
// 8 i x 4 j outputs. k tile in smem (reused via registers across 4 j),
// q streamed from global (16B-stride -> L1 line hits), packed f32x2 math.

namespace {
constexpr int S  = 1024;
constexpr int H  = 8;
constexpr int D  = 64;
constexpr int NT = 256;
constexpr int TI = 8;     // i per block == i per thread
constexpr int JB = 128;   // j per block (8 warps * 4 jl * 4 u)
constexpr int ROWPAD = 68; // 64 + 4: h-rows hit distinct bank quads

typedef unsigned long long ull;

__device__ __forceinline__ ull addx2(ull a, ull b) {
    ull r;
    asm("add.rn.f32x2 %0, %1, %2;" : "=l"(r) : "l"(a), "l"(b));
    return r;
}
}  // namespace

__global__ void __launch_bounds__(NT, 2) l1attn_kernel(
    const float* __restrict__ qg,
    const float* __restrict__ kg,
    float* __restrict__ out)
{
    __shared__ __align__(16) float ks[TI * H * ROWPAD];  // 64 rows x 68 = 17408 B

    const int t  = threadIdx.x;
    const int j0 = blockIdx.x * JB;
    const int i0 = blockIdx.y * TI;
    const int b  = blockIdx.z;

    // ---- Stage k tile: rows (ii*8 + h), 64 floats each ----
    {
        const float* kb = kg + ((size_t)b * S + i0) * (size_t)(H * D);
        #pragma unroll
        for (int r = 0; r < (TI * H * D) / (4 * NT); r++) {  // 4 iters
            int idx = t + r * NT;       // float4 index 0..1023
            int row = idx >> 4;         // (ii*8 + h), 16 float4 per row
            int dd  = (idx & 15) << 2;
            float4 v = *reinterpret_cast<const float4*>(kb + row * D + dd);
            *reinterpret_cast<float4*>(&ks[row * ROWPAD + dd]) = v;
        }
    }
    __syncthreads();

    const int h  = t & 7;          // 0..7
    const int jl = (t >> 3) & 3;   // 0..3
    const int w  = t >> 5;         // warp 0..7
    const int jbase = j0 + w * 16 + jl;  // u stride = 4 j

    const ull SGN = 0x8000000080000000ULL;
    const ull MSK = 0x7FFFFFFF7FFFFFFFULL;

    const float* qrow = qg + (((size_t)b * S + jbase) * H + h) * D;
    constexpr int QU = 4 * H * D;  // float stride between u's q rows (j += 4)

    ull acc[TI][4];
    #pragma unroll
    for (int i = 0; i < TI; i++)
        #pragma unroll
        for (int u = 0; u < 4; u++) acc[i][u] = 0ULL;

    // d in 16 chunks of 4; keep c-loop rolled so body (~220 instr) stays in L0 I$.
    #pragma unroll 1
    for (int c = 0; c < D / 4; c++) {
        // q chunk for the 4 j's, pre-negated via sign XOR (|q-k| == |k-q|).
        ull nq[4][2];
        #pragma unroll
        for (int u = 0; u < 4; u++) {
            ulonglong2 qv = *reinterpret_cast<const ulonglong2*>(qrow + u * QU + c * 4);
            nq[u][0] = qv.x ^ SGN;
            nq[u][1] = qv.y ^ SGN;
        }
        const float* krow = &ks[h * ROWPAD + c * 4];
        #pragma unroll
        for (int i = 0; i < TI; i++) {
            ulonglong2 kv = *reinterpret_cast<const ulonglong2*>(krow + i * (8 * ROWPAD));
            #pragma unroll
            for (int u = 0; u < 4; u++) {
                ull t0 = addx2(kv.x, nq[u][0]) & MSK;   // |k-q| packed, d pair 0
                ull t1 = addx2(kv.y, nq[u][1]) & MSK;   // d pair 1
                acc[i][u] = addx2(acc[i][u], addx2(t0, t1));
            }
        }
    }

    // ---- Epilogue: reduce packed halves, scale, coalesced stores ----
    const float scale = -0.125f;  // -1/sqrt(64)
    #pragma unroll
    for (int i = 0; i < TI; i++) {
        const size_t ob = (((size_t)b * S + (i0 + i)) * S + jbase) * H + h;
        #pragma unroll
        for (int u = 0; u < 4; u++) {
            unsigned int lo = (unsigned int)(acc[i][u] & 0xffffffffu);
            unsigned int hi = (unsigned int)(acc[i][u] >> 32);
            out[ob + (size_t)u * (4 * H)] =
                (__uint_as_float(lo) + __uint_as_float(hi)) * scale;
        }
    }
}

extern "C" void kernel_launch(void* const* d_in, const int* in_sizes, int n_in,
                              void* d_out, int out_size) {
    const float* q = (const float*)d_in[0];
    const float* k = (const float*)d_in[1];
    float* out     = (float*)d_out;

    const int B = in_sizes[0] / (S * H * D);  // = 8
    dim3 grid(S / JB, S / TI, B);
    l1attn_kernel<<<grid, NT>>>(q, k, out);
}